// round 3
// baseline (speedup 1.0000x reference)
#include <cuda_runtime.h>
#include <math.h>

#define BB  512
#define SSL 128
#define HH  192
#define VV  256
#define PP  64
#define PHD 16
#define BT  4
#define NTH 384

typedef unsigned long long u64;

struct SMLayout {
    // activations stored duplicated: X[c][r] = (v, v)
    float2 tok  [HH][BT];
    float2 prevb[HH][BT];
    float2 patch[HH][BT];
    float2 sec  [HH][BT];
    float2 phs  [HH][BT];
    float2 succ [HH][BT];
    float2 htmp [HH][BT];
    float2 pwb  [PP][BT];
    float2 phwb [PHD][BT];
    float4 partbuf[NTH][4];     // per-thread 4-col x 4-row partials (col-major float4 over rows)
    float  rlog[PHD][BT];
    float  gatev[BT];
    float  lnmean[BT], lnrstd[BT];
    int    sidx[BT][SSL];
};

__device__ __forceinline__ float gelu_exact(float x) {
    return 0.5f * x * (1.0f + erff(x * 0.70710678118654752440f));
}
__device__ __forceinline__ float sigmoidf_(float x) {
    return 1.0f / (1.0f + expf(-x));
}
__device__ __forceinline__ u64 ffma2u(u64 a, u64 b, u64 c) {
    u64 d;
    asm("fma.rn.f32x2 %0, %1, %2, %3;" : "=l"(d) : "l"(a), "l"(b), "l"(c));
    return d;
}

// 4 cols (c0..c0+3) x 4 rows register tile, packed pairs.
// ac[r][p]: p=0 -> cols (c0,c0+1), p=1 -> cols (c0+2,c0+3), for batch row r.
template<int NIT>
__device__ __forceinline__ void seg4(
    u64 (&ac)[4][2],
    const float2 (*__restrict__ X)[BT], const float* __restrict__ W,
    int xrow0, int wrow0, int Ns, int c0)
{
    #pragma unroll 8
    for (int k = 0; k < NIT; ++k) {
        ulonglong2 w2 = *(const ulonglong2*)(W + (size_t)(wrow0 + k) * Ns + c0);
        ulonglong2 xa = *(const ulonglong2*)&X[xrow0 + k][0];  // (x0,x0),(x1,x1)
        ulonglong2 xb = *(const ulonglong2*)&X[xrow0 + k][2];  // (x2,x2),(x3,x3)
        ac[0][0] = ffma2u(w2.x, xa.x, ac[0][0]);
        ac[0][1] = ffma2u(w2.y, xa.x, ac[0][1]);
        ac[1][0] = ffma2u(w2.x, xa.y, ac[1][0]);
        ac[1][1] = ffma2u(w2.y, xa.y, ac[1][1]);
        ac[2][0] = ffma2u(w2.x, xb.x, ac[2][0]);
        ac[2][1] = ffma2u(w2.y, xb.x, ac[2][1]);
        ac[3][0] = ffma2u(w2.x, xb.y, ac[3][0]);
        ac[3][1] = ffma2u(w2.y, xb.y, ac[3][1]);
    }
}

#define F2X(u) (((float2*)&(u))->x)
#define F2Y(u) (((float2*)&(u))->y)

#define PART_STORE()                                                                          \
    s->partbuf[t][0] = make_float4(F2X(ac[0][0]),F2X(ac[1][0]),F2X(ac[2][0]),F2X(ac[3][0]));  \
    s->partbuf[t][1] = make_float4(F2Y(ac[0][0]),F2Y(ac[1][0]),F2Y(ac[2][0]),F2Y(ac[3][0]));  \
    s->partbuf[t][2] = make_float4(F2X(ac[0][1]),F2X(ac[1][1]),F2X(ac[2][1]),F2X(ac[3][1]));  \
    s->partbuf[t][3] = make_float4(F2Y(ac[0][1]),F2Y(ac[1][1]),F2Y(ac[2][1]),F2Y(ac[3][1]));

#define REDUCE_SUM(NGP, PCH)                                        \
    int gg = t >> 2, cc = t & 3;                                    \
    float4 sv = s->partbuf[gg][cc];                                 \
    _Pragma("unroll")                                               \
    for (int pp = 1; pp < (PCH); ++pp) {                            \
        float4 v = s->partbuf[pp * (NGP) + gg][cc];                 \
        sv.x += v.x; sv.y += v.y; sv.z += v.z; sv.w += v.w;         \
    }

// write duplicated activation float4 pairs: X[t] = {(a,a),(b,b),(c,c),(d,d)}
#define WRITE_DUP(X, v)                                             \
    *(float4*)&(X)[t][0] = make_float4((v).x, (v).x, (v).y, (v).y); \
    *(float4*)&(X)[t][2] = make_float4((v).z, (v).z, (v).w, (v).w);

__global__ __launch_bounds__(NTH, 1)
void spike_recurrence_kernel(
    const int*   __restrict__ input_ids,
    const float* __restrict__ emb,
    const float* __restrict__ sel_W,  const float* __restrict__ sel_b,
    const float* __restrict__ patch_values,
    const float* __restrict__ bind_W1, const float* __restrict__ bind_b1,
    const float* __restrict__ bind_W2, const float* __restrict__ bind_b2,
    const float* __restrict__ phase_embed,
    const float* __restrict__ router_W, const float* __restrict__ router_b,
    const float* __restrict__ succ_W1, const float* __restrict__ succ_b1,
    const float* __restrict__ succ_W2, const float* __restrict__ succ_b2,
    const float* __restrict__ gate_W1, const float* __restrict__ gate_b1,
    const float* __restrict__ gate_W2, const float* __restrict__ gate_b2,
    const float* __restrict__ ln_g,   const float* __restrict__ ln_b,
    const float* __restrict__ dec_W,
    float* __restrict__ out)
{
    extern __shared__ __align__(16) char smraw[];
    SMLayout* s = (SMLayout*)smraw;

    const int t    = threadIdx.x;
    const int lane = t & 31;
    const int warp = t >> 5;
    const int bbase = blockIdx.x * BT;

    for (int i = t; i < BT * SSL; i += NTH) {
        int r = i / SSL, ss = i % SSL;
        s->sidx[r][ss] = input_ids[(bbase + r) * SSL + ss];
    }
    if (t < HH) {
        *(float4*)&s->prevb[t][0] = make_float4(0.f, 0.f, 0.f, 0.f);
        *(float4*)&s->prevb[t][2] = make_float4(0.f, 0.f, 0.f, 0.f);
    }
    __syncthreads();

    const size_t OFF_HID = (size_t)BB * SSL * VV;
    const size_t OFF_PW  = OFF_HID + (size_t)BB * SSL * HH;
    const size_t OFF_PHW = OFF_PW  + (size_t)BB * SSL * PP;
    const size_t OFF_GT  = OFF_PHW + (size_t)BB * SSL * PHD;

    for (int st = 0; st < SSL; ++st) {
        // ---- token embedding gather (duplicated) -------------------------
        for (int i = t; i < HH * BT; i += NTH) {
            int r = i / HH, c = i % HH;
            float e = emb[(size_t)s->sidx[r][st] * HH + c];
            s->tok[c][r] = make_float2(e, e);
        }
        __syncthreads();

        // ---- sel: [tok,prev] @ sel_W  (N=64, NG=16, P=24, kpp=8+8) -------
        {
            int g = t % 16, p = t / 16, c0 = 4 * g;
            u64 ac[4][2] = {};
            seg4<8>(ac, s->tok,   sel_W, p * 8,       p * 8, PP, c0);
            seg4<8>(ac, s->prevb, sel_W, p * 8, 192 + p * 8, PP, c0);
            PART_STORE();
        }
        __syncthreads();
        if (t < PP) {
            REDUCE_SUM(16, 24);
            float bias = sel_b[t];
            sv.x += bias; sv.y += bias; sv.z += bias; sv.w += bias;
            WRITE_DUP(s->pwb, sv);
        }
        __syncthreads();
        if (warp < BT) {  // softmax over 64, one warp per batch row
            int r = warp;
            float v0 = s->pwb[lane][r].x, v1 = s->pwb[lane + 32][r].x;
            float m = fmaxf(v0, v1);
            #pragma unroll
            for (int o = 16; o > 0; o >>= 1) m = fmaxf(m, __shfl_xor_sync(0xffffffffu, m, o));
            float e0 = expf(v0 - m), e1 = expf(v1 - m);
            float sm = e0 + e1;
            #pragma unroll
            for (int o = 16; o > 0; o >>= 1) sm += __shfl_xor_sync(0xffffffffu, sm, o);
            float inv = 1.0f / sm;
            e0 *= inv; e1 *= inv;
            s->pwb[lane][r] = make_float2(e0, e0);
            s->pwb[lane + 32][r] = make_float2(e1, e1);
            size_t ob = OFF_PW + ((size_t)(bbase + r) * SSL + st) * PP;
            out[ob + lane] = e0; out[ob + lane + 32] = e1;
        }
        __syncthreads();

        // ---- patch = pw @ patch_values  (N=192, NG=48, P=8, kpp=8) -------
        {
            int g = t % 48, p = t / 48, c0 = 4 * g;
            u64 ac[4][2] = {};
            seg4<8>(ac, s->pwb, patch_values, p * 8, p * 8, HH, c0);
            PART_STORE();
        }
        __syncthreads();
        if (t < HH) {
            REDUCE_SUM(48, 8);
            WRITE_DUP(s->patch, sv);
        }
        __syncthreads();

        // ---- bind1: [tok,patch,prev] @ bind_W1 -> gelu  (kpp=3x24) -------
        {
            int g = t % 48, p = t / 48, c0 = 4 * g;
            u64 ac[4][2] = {};
            seg4<24>(ac, s->tok,   bind_W1, p * 24,        p * 24, HH, c0);
            seg4<24>(ac, s->patch, bind_W1, p * 24,  192 + p * 24, HH, c0);
            seg4<24>(ac, s->prevb, bind_W1, p * 24,  384 + p * 24, HH, c0);
            PART_STORE();
        }
        __syncthreads();
        if (t < HH) {
            REDUCE_SUM(48, 8);
            float b1 = bind_b1[t];
            float4 h;
            h.x = gelu_exact(sv.x + b1); h.y = gelu_exact(sv.y + b1);
            h.z = gelu_exact(sv.z + b1); h.w = gelu_exact(sv.w + b1);
            WRITE_DUP(s->htmp, h);
        }
        __syncthreads();

        // ---- bind2: htmp @ bind_W2 -> tanh -------------------------------
        {
            int g = t % 48, p = t / 48, c0 = 4 * g;
            u64 ac[4][2] = {};
            seg4<24>(ac, s->htmp, bind_W2, p * 24, p * 24, HH, c0);
            PART_STORE();
        }
        __syncthreads();
        if (t < HH) {
            REDUCE_SUM(48, 8);
            float b2 = bind_b2[t];
            float4 h;
            h.x = tanhf(sv.x + b2); h.y = tanhf(sv.y + b2);
            h.z = tanhf(sv.z + b2); h.w = tanhf(sv.w + b2);
            WRITE_DUP(s->sec, h);
        }
        __syncthreads();

        // ---- router: [sec,prev] @ router_W  (N=16, NG=4, P=96, kpp=2+2) --
        {
            int g = t % 4, p = t / 4, c0 = 4 * g;
            u64 ac[4][2] = {};
            seg4<2>(ac, s->sec,   router_W, p * 2,       p * 2, PHD, c0);
            seg4<2>(ac, s->prevb, router_W, p * 2, 192 + p * 2, PHD, c0);
            PART_STORE();
        }
        __syncthreads();
        if (t < PHD) {
            REDUCE_SUM(4, 96);
            float bias = router_b[t];
            sv.x += bias; sv.y += bias; sv.z += bias; sv.w += bias;
            *(float4*)&s->rlog[t][0] = sv;
        }
        __syncthreads();
        if (t < BT) {
            int r = t;
            float m = -1e30f;
            #pragma unroll
            for (int c = 0; c < PHD; ++c) m = fmaxf(m, s->rlog[c][r]);
            float sm = 0.f;
            float e[PHD];
            #pragma unroll
            for (int c = 0; c < PHD; ++c) { e[c] = expf(s->rlog[c][r] - m); sm += e[c]; }
            float inv = 1.0f / sm;
            size_t ob = OFF_PHW + ((size_t)(bbase + r) * SSL + st) * PHD;
            #pragma unroll
            for (int c = 0; c < PHD; ++c) {
                float v = e[c] * inv;
                s->phwb[c][r] = make_float2(v, v);
                out[ob + c] = v;
            }
        }
        __syncthreads();

        // ---- phs = phw @ phase_embed  (N=192, K=16, kpp=2) ---------------
        {
            int g = t % 48, p = t / 48, c0 = 4 * g;
            u64 ac[4][2] = {};
            seg4<2>(ac, s->phwb, phase_embed, p * 2, p * 2, HH, c0);
            PART_STORE();
        }
        __syncthreads();
        if (t < HH) {
            REDUCE_SUM(48, 8);
            WRITE_DUP(s->phs, sv);
        }
        __syncthreads();

        // ---- succ1: [sec,patch,phs] @ succ_W1 -> gelu --------------------
        {
            int g = t % 48, p = t / 48, c0 = 4 * g;
            u64 ac[4][2] = {};
            seg4<24>(ac, s->sec,   succ_W1, p * 24,        p * 24, HH, c0);
            seg4<24>(ac, s->patch, succ_W1, p * 24,  192 + p * 24, HH, c0);
            seg4<24>(ac, s->phs,   succ_W1, p * 24,  384 + p * 24, HH, c0);
            PART_STORE();
        }
        __syncthreads();
        if (t < HH) {
            REDUCE_SUM(48, 8);
            float b1 = succ_b1[t];
            float4 h;
            h.x = gelu_exact(sv.x + b1); h.y = gelu_exact(sv.y + b1);
            h.z = gelu_exact(sv.z + b1); h.w = gelu_exact(sv.w + b1);
            WRITE_DUP(s->htmp, h);
        }
        __syncthreads();

        // ---- succ2: htmp @ succ_W2 -> tanh --------------------------------
        {
            int g = t % 48, p = t / 48, c0 = 4 * g;
            u64 ac[4][2] = {};
            seg4<24>(ac, s->htmp, succ_W2, p * 24, p * 24, HH, c0);
            PART_STORE();
        }
        __syncthreads();
        if (t < HH) {
            REDUCE_SUM(48, 8);
            float b2 = succ_b2[t];
            float4 h;
            h.x = tanhf(sv.x + b2); h.y = tanhf(sv.y + b2);
            h.z = tanhf(sv.z + b2); h.w = tanhf(sv.w + b2);
            WRITE_DUP(s->succ, h);
        }
        __syncthreads();

        // ---- gate: [succ,prev] @ gate_W1 -> gelu * gate_W2 ----------------
        {
            int g = t % 48, p = t / 48, c0 = 4 * g;
            u64 ac[4][2] = {};
            seg4<24>(ac, s->succ,  gate_W1, p * 24,        p * 24, HH, c0);
            seg4<24>(ac, s->prevb, gate_W1, p * 24,  192 + p * 24, HH, c0);
            PART_STORE();
        }
        __syncthreads();
        if (t < HH) {
            REDUCE_SUM(48, 8);
            float b1 = gate_b1[t];
            float w2 = gate_W2[t];
            float4 h;
            h.x = gelu_exact(sv.x + b1) * w2; h.y = gelu_exact(sv.y + b1) * w2;
            h.z = gelu_exact(sv.z + b1) * w2; h.w = gelu_exact(sv.w + b1) * w2;
            WRITE_DUP(s->htmp, h);
        }
        __syncthreads();
        if (warp < BT) {
            int r = warp;
            float sg = 0.f;
            #pragma unroll
            for (int j = 0; j < 6; ++j) sg += s->htmp[lane + 32 * j][r].x;
            #pragma unroll
            for (int o = 16; o > 0; o >>= 1) sg += __shfl_xor_sync(0xffffffffu, sg, o);
            if (lane == 0) {
                float gv = sigmoidf_(sg + gate_b2[0]);
                s->gatev[r] = gv;
                out[OFF_GT + (size_t)(bbase + r) * SSL + st] = gv;
            }
        }
        __syncthreads();

        // ---- hidden blend + LayerNorm --------------------------------------
        if (t < HH) {
            float4 h;
            h.x = s->gatev[0] * s->succ[t][0].x + (1.f - s->gatev[0]) * s->prevb[t][0].x;
            h.y = s->gatev[1] * s->succ[t][1].x + (1.f - s->gatev[1]) * s->prevb[t][1].x;
            h.z = s->gatev[2] * s->succ[t][2].x + (1.f - s->gatev[2]) * s->prevb[t][2].x;
            h.w = s->gatev[3] * s->succ[t][3].x + (1.f - s->gatev[3]) * s->prevb[t][3].x;
            WRITE_DUP(s->htmp, h);
        }
        __syncthreads();
        if (warp < BT) {
            int r = warp;
            float sm = 0.f, sq = 0.f;
            #pragma unroll
            for (int j = 0; j < 6; ++j) {
                float v = s->htmp[lane + 32 * j][r].x;
                sm += v; sq += v * v;
            }
            #pragma unroll
            for (int o = 16; o > 0; o >>= 1) {
                sm += __shfl_xor_sync(0xffffffffu, sm, o);
                sq += __shfl_xor_sync(0xffffffffu, sq, o);
            }
            if (lane == 0) {
                float mean = sm * (1.0f / HH);
                float var  = sq * (1.0f / HH) - mean * mean;
                s->lnmean[r] = mean;
                s->lnrstd[r] = rsqrtf(var + 1e-5f);
            }
        }
        __syncthreads();
        if (t < HH) {
            float g = ln_g[t], bb = ln_b[t];
            float4 o;
            o.x = (s->htmp[t][0].x - s->lnmean[0]) * s->lnrstd[0] * g + bb;
            o.y = (s->htmp[t][1].x - s->lnmean[1]) * s->lnrstd[1] * g + bb;
            o.z = (s->htmp[t][2].x - s->lnmean[2]) * s->lnrstd[2] * g + bb;
            o.w = (s->htmp[t][3].x - s->lnmean[3]) * s->lnrstd[3] * g + bb;
            WRITE_DUP(s->prevb, o);   // carry for next step
            #pragma unroll
            for (int r = 0; r < BT; ++r)
                out[OFF_HID + ((size_t)(bbase + r) * SSL + st) * HH + t] =
                    (r == 0) ? o.x : (r == 1) ? o.y : (r == 2) ? o.z : o.w;
        }
        __syncthreads();

        // ---- decoder logits  (N=256, NG=64, P=6, kpp=32) -------------------
        {
            int g = t % 64, p = t / 64, c0 = 4 * g;
            u64 ac[4][2] = {};
            seg4<32>(ac, s->prevb, dec_W, p * 32, p * 32, VV, c0);
            PART_STORE();
        }
        __syncthreads();
        if (t < VV) {
            REDUCE_SUM(64, 6);
            #pragma unroll
            for (int r = 0; r < BT; ++r) {
                size_t ob = ((size_t)(bbase + r) * SSL + st) * VV;
                float v = (r == 0) ? sv.x : (r == 1) ? sv.y : (r == 2) ? sv.z : sv.w;
                out[ob + t] = v;
            }
        }
        __syncthreads();
    }
}

extern "C" void kernel_launch(void* const* d_in, const int* in_sizes, int n_in,
                              void* d_out, int out_size) {
    const int*   input_ids    = (const int*)  d_in[0];
    const float* emb          = (const float*)d_in[1];
    const float* sel_W        = (const float*)d_in[2];
    const float* sel_b        = (const float*)d_in[3];
    const float* patch_values = (const float*)d_in[4];
    const float* bind_W1      = (const float*)d_in[5];
    const float* bind_b1      = (const float*)d_in[6];
    const float* bind_W2      = (const float*)d_in[7];
    const float* bind_b2      = (const float*)d_in[8];
    const float* phase_embed  = (const float*)d_in[9];
    const float* router_W     = (const float*)d_in[10];
    const float* router_b     = (const float*)d_in[11];
    const float* succ_W1      = (const float*)d_in[12];
    const float* succ_b1      = (const float*)d_in[13];
    const float* succ_W2      = (const float*)d_in[14];
    const float* succ_b2      = (const float*)d_in[15];
    const float* gate_W1      = (const float*)d_in[16];
    const float* gate_b1      = (const float*)d_in[17];
    const float* gate_W2      = (const float*)d_in[18];
    const float* gate_b2      = (const float*)d_in[19];
    const float* ln_g         = (const float*)d_in[20];
    const float* ln_b         = (const float*)d_in[21];
    const float* dec_W        = (const float*)d_in[22];
    float* out = (float*)d_out;

    cudaFuncSetAttribute(spike_recurrence_kernel,
                         cudaFuncAttributeMaxDynamicSharedMemorySize,
                         (int)sizeof(SMLayout));

    spike_recurrence_kernel<<<BB / BT, NTH, sizeof(SMLayout)>>>(
        input_ids, emb, sel_W, sel_b, patch_values,
        bind_W1, bind_b1, bind_W2, bind_b2,
        phase_embed, router_W, router_b,
        succ_W1, succ_b1, succ_W2, succ_b2,
        gate_W1, gate_b1, gate_W2, gate_b2,
        ln_g, ln_b, dec_W, out);
}